// round 1
// baseline (speedup 1.0000x reference)
#include <cuda_runtime.h>
#include <math_constants.h>

#define NROWS 4096
#define S_SLOTS 200
#define X_DIM 64
#define M_DIM 364
#define O_DIM 64
#define F4 91          // M_DIM / 4
#define EPS 1e-6f
#define NT 256
#define NW 8

__global__ __launch_bounds__(NT, 2)
void mem_attn_kernel(const float* __restrict__ x,
                     const float* __restrict__ mem,
                     const float* __restrict__ W_x,
                     const float* __restrict__ b_x,
                     const float* __restrict__ W_out,
                     const float* __restrict__ b_out,
                     float* __restrict__ out)
{
    __shared__ __align__(16) float sh_x[X_DIM];
    __shared__ __align__(16) float sh_h[M_DIM];
    __shared__ __align__(16) float sh_acc[NW][M_DIM];
    __shared__ float sh_wmax[NW];
    __shared__ float sh_wsum[NW];
    __shared__ float sh_red[NW];
    __shared__ __align__(16) float sh_g[M_DIM];
    __shared__ float sh_out[4][O_DIM];

    const int n    = blockIdx.x;
    const int t    = threadIdx.x;
    const int lane = t & 31;
    const int w    = t >> 5;

    // ---- load x row ----
    if (t < X_DIM) sh_x[t] = x[(size_t)n * X_DIM + t];
    __syncthreads();

    // ---- h = relu(x @ W_x + b_x), and partial ||h||^2 ----
    float hn_part = 0.f;
    for (int j = t; j < M_DIM; j += NT) {
        float a = b_x[j];
        #pragma unroll 16
        for (int i = 0; i < X_DIM; i++) a = fmaf(sh_x[i], W_x[i * M_DIM + j], a);
        a = fmaxf(a, 0.f);
        sh_h[j] = a;
        hn_part = fmaf(a, a, hn_part);
    }
    #pragma unroll
    for (int o = 16; o > 0; o >>= 1) hn_part += __shfl_xor_sync(0xffffffffu, hn_part, o);
    if (lane == 0) sh_red[w] = hn_part;
    __syncthreads();
    float hsum = 0.f;
    #pragma unroll
    for (int i = 0; i < NW; i++) hsum += sh_red[i];
    const float hnorm = fmaxf(sqrtf(hsum), EPS);

    // ---- single-pass over mem with online softmax accumulation ----
    // warp w handles slots s = w, w+8, ... (25 each). Lane holds float4 chunks
    // idx = lane, lane+32, lane+64 (valid when < 91).
    float4 acc0 = make_float4(0.f, 0.f, 0.f, 0.f);
    float4 acc1 = make_float4(0.f, 0.f, 0.f, 0.f);
    float4 acc2 = make_float4(0.f, 0.f, 0.f, 0.f);
    float rmax = -CUDART_INF_F;
    float rsum = 0.f;

    const float* memn = mem + (size_t)n * S_SLOTS * M_DIM;
    const float4* sh_h4 = reinterpret_cast<const float4*>(sh_h);

    const bool has2 = (lane + 64) < F4;   // lanes 0..26

    for (int s = w; s < S_SLOTS; s += NW) {
        const float4* row = reinterpret_cast<const float4*>(memn + (size_t)s * M_DIM);
        float4 v0 = __ldcs(row + lane);
        float4 v1 = __ldcs(row + lane + 32);
        float4 v2 = has2 ? __ldcs(row + lane + 64) : make_float4(0.f, 0.f, 0.f, 0.f);

        float4 h0 = sh_h4[lane];
        float4 h1 = sh_h4[lane + 32];
        float4 h2 = has2 ? sh_h4[lane + 64] : make_float4(0.f, 0.f, 0.f, 0.f);

        float dot = v0.x*h0.x + v0.y*h0.y + v0.z*h0.z + v0.w*h0.w
                  + v1.x*h1.x + v1.y*h1.y + v1.z*h1.z + v1.w*h1.w
                  + v2.x*h2.x + v2.y*h2.y + v2.z*h2.z + v2.w*h2.w;
        float nsq = v0.x*v0.x + v0.y*v0.y + v0.z*v0.z + v0.w*v0.w
                  + v1.x*v1.x + v1.y*v1.y + v1.z*v1.z + v1.w*v1.w
                  + v2.x*v2.x + v2.y*v2.y + v2.z*v2.z + v2.w*v2.w;
        #pragma unroll
        for (int o = 16; o > 0; o >>= 1) {
            dot += __shfl_xor_sync(0xffffffffu, dot, o);
            nsq += __shfl_xor_sync(0xffffffffu, nsq, o);
        }

        const float mnorm = fmaxf(sqrtf(nsq), EPS);
        const float sim   = dot / (mnorm * hnorm);

        const float nmax = fmaxf(rmax, sim);
        const float csc  = __expf(rmax - nmax);   // exp(-inf)=0 on first iter
        const float e    = __expf(sim - nmax);
        rmax = nmax;
        rsum = rsum * csc + e;

        acc0.x = acc0.x*csc + e*v0.x;  acc0.y = acc0.y*csc + e*v0.y;
        acc0.z = acc0.z*csc + e*v0.z;  acc0.w = acc0.w*csc + e*v0.w;
        acc1.x = acc1.x*csc + e*v1.x;  acc1.y = acc1.y*csc + e*v1.y;
        acc1.z = acc1.z*csc + e*v1.z;  acc1.w = acc1.w*csc + e*v1.w;
        acc2.x = acc2.x*csc + e*v2.x;  acc2.y = acc2.y*csc + e*v2.y;
        acc2.z = acc2.z*csc + e*v2.z;  acc2.w = acc2.w*csc + e*v2.w;
    }

    // ---- merge warps (split softmax) ----
    if (lane == 0) { sh_wmax[w] = rmax; sh_wsum[w] = rsum; }
    __syncthreads();

    float gmax = -CUDART_INF_F;
    #pragma unroll
    for (int i = 0; i < NW; i++) gmax = fmaxf(gmax, sh_wmax[i]);
    float total = 0.f;
    #pragma unroll
    for (int i = 0; i < NW; i++) total += sh_wsum[i] * __expf(sh_wmax[i] - gmax);

    const float factor = __expf(rmax - gmax);
    float4* dst = reinterpret_cast<float4*>(sh_acc[w]);
    {
        float4 a;
        a.x = acc0.x*factor; a.y = acc0.y*factor; a.z = acc0.z*factor; a.w = acc0.w*factor;
        dst[lane] = a;
        a.x = acc1.x*factor; a.y = acc1.y*factor; a.z = acc1.z*factor; a.w = acc1.w*factor;
        dst[lane + 32] = a;
        if (has2) {
            a.x = acc2.x*factor; a.y = acc2.y*factor; a.z = acc2.z*factor; a.w = acc2.w*factor;
            dst[lane + 64] = a;
        }
    }
    __syncthreads();

    const float inv = 1.f / (total * (float)S_SLOTS);
    for (int j = t; j < M_DIM; j += NT) {
        float p = 0.f;
        #pragma unroll
        for (int i = 0; i < NW; i++) p += sh_acc[i][j];
        sh_g[j] = p * inv * sh_h[j];
    }
    __syncthreads();

    // ---- out = relu((pooled*h) @ W_out + b_out) ----
    {
        const int oc = t & 63;
        const int c  = t >> 6;           // 4 chunks of 91
        float a = 0.f;
        const int m0 = c * F4;
        #pragma unroll 13
        for (int m = m0; m < m0 + F4; m++) a = fmaf(sh_g[m], W_out[m * O_DIM + oc], a);
        sh_out[c][oc] = a;
    }
    __syncthreads();
    if (t < O_DIM) {
        float a = sh_out[0][t] + sh_out[1][t] + sh_out[2][t] + sh_out[3][t] + b_out[t];
        out[(size_t)n * O_DIM + t] = fmaxf(a, 0.f);
    }
}

extern "C" void kernel_launch(void* const* d_in, const int* in_sizes, int n_in,
                              void* d_out, int out_size)
{
    const float* x     = (const float*)d_in[0];
    const float* mem   = (const float*)d_in[1];
    const float* W_x   = (const float*)d_in[2];
    const float* b_x   = (const float*)d_in[3];
    const float* W_out = (const float*)d_in[4];
    const float* b_out = (const float*)d_in[5];
    float* out = (float*)d_out;

    mem_attn_kernel<<<NROWS, NT>>>(x, mem, W_x, b_x, W_out, b_out, out);
}